// round 15
// baseline (speedup 1.0000x reference)
#include <cuda_runtime.h>

#define NPIX   (1024*1024)
#define TPB    512
#define NWARP  (TPB/32)              // 16
#define NCTA   148
#define PIXPAD 7168                  // = 2 * 7 * TPB exactly
#define NPAIRS (PIXPAD/2)            // 3584 = 7*TPB -> fixed trip count 7
#define KTRIPS 7
#define EPSF   1e-8f
#define NITER  100

typedef unsigned long long ull;

// ---------------- packed f32x2 helpers --------------------------------------
#define FMA2(d,a,b,c) asm("fma.rn.f32x2 %0, %1, %2, %3;" : "=l"(d) : "l"(a), "l"(b), "l"(c))
#define MUL2(d,a,b)   asm("mul.rn.f32x2 %0, %1, %2;"     : "=l"(d) : "l"(a), "l"(b))

__device__ __forceinline__ ull pk(float lo, float hi) {
    ull r; asm("mov.b64 %0, {%1,%2};" : "=l"(r) : "f"(lo), "f"(hi)); return r;
}
__device__ __forceinline__ void upk(ull v, float& lo, float& hi) {
    asm("mov.b64 {%0,%1}, %2;" : "=f"(lo), "=f"(hi) : "l"(v));
}
__device__ __forceinline__ float frcp(float x) {
    float r; asm("rcp.approx.f32 %0, %1;" : "=f"(r) : "f"(x)); return r;
}
__device__ __forceinline__ ull rcp2(ull v) {
    float a, b; upk(v, a, b); return pk(frcp(a), frcp(b));
}

// ---------------- device globals (scratch; zeroed each launch by hx_init) ---
__device__ unsigned g_bar;               // arrival counter (own line)
__device__ unsigned g_pad0[63];
__device__ unsigned g_rel;               // release epoch (separate read-only line)
__device__ unsigned g_pad1[63];
__device__ unsigned g_h0[2048];
__device__ unsigned g_h1[2048];
__device__ unsigned g_h2[1024];
__device__ float    g_part[2][22 * 160];

__global__ void hx_init() {
    int t = blockIdx.x * blockDim.x + threadIdx.x;
    if (t == 0) { g_bar = 0u; g_rel = 0u; }
    if (t < 2048) { g_h0[t] = 0u; g_h1[t] = 0u; }
    if (t < 1024) g_h2[t] = 0u;
}

// ---------------- two-level grid barrier (148 co-resident CTAs) --------------
// Arrival: R10's single-counter atomicAdd (fastest measured). Wait: only CTA 0
// spins on the RMW line; it publishes a release epoch on a clean separate line
// that the other 147 CTAs poll (read-only broadcast; no RMW interference).
__device__ __forceinline__ void gsync(int cta, unsigned epoch) {
    __syncthreads();
    if (threadIdx.x == 0) {
        __threadfence();                                      // release partials
        atomicAdd(&g_bar, 1u);
        if (cta == 0) {
            while (*(volatile unsigned*)&g_bar < epoch * NCTA) { }
            __threadfence();
            *(volatile unsigned*)&g_rel = epoch;
        } else {
            while (*(volatile unsigned*)&g_rel < epoch) { }
        }
        __threadfence();                                      // acquire
    }
    __syncthreads();
}

// ---------------- warp-0 bin search for radix select -------------------------
__device__ __forceinline__ void find_bin(const unsigned* hist, int nb, unsigned r,
                                         unsigned* sel_out) {
    int lane = threadIdx.x & 31;
    int ch = nb >> 5;
    unsigned csum = 0;
    for (int i = 0; i < ch; ++i) csum += __ldcg(&hist[lane * ch + i]);
    unsigned inc = csum;
#pragma unroll
    for (int off = 1; off < 32; off <<= 1) {
        unsigned t = __shfl_up_sync(0xffffffffu, inc, off);
        if (lane >= off) inc += t;
    }
    unsigned excl = inc - csum;
    bool has = (r >= excl) && (r < inc);
    unsigned m = __ballot_sync(0xffffffffu, has);
    int sel = __ffs(m) - 1;
    unsigned bin = 0, before = 0;
    if (lane == sel) {
        unsigned c = excl;
        for (int i = 0; i < ch; ++i) {
            unsigned h = __ldcg(&hist[sel * ch + i]);
            if (r < c + h) { bin = (unsigned)(sel * ch + i); before = c; break; }
            c += h;
        }
    }
    bin    = __shfl_sync(0xffffffffu, bin, sel);
    before = __shfl_sync(0xffffffffu, before, sel);
    if (lane == 0) { sel_out[0] = bin; sel_out[1] = before; }
}

// warp-aggregated histogram add (all 32 lanes participate)
__device__ __forceinline__ void hist_add(unsigned* sHist, unsigned bin, bool active) {
    unsigned key = active ? bin : 0xffffffffu;
    unsigned mask = __match_any_sync(0xffffffffu, key);
    int leader = __ffs(mask) - 1;
    if (active && (int)(threadIdx.x & 31) == leader)
        atomicAdd(&sHist[bin], (unsigned)__popc(mask));
}

// ---------------- the persistent kernel --------------------------------------
__global__ void __launch_bounds__(TPB, 1)
he_norm_kernel(const float* __restrict__ pic, const float* __restrict__ Wt,
               const float* __restrict__ HtRM, const float* __restrict__ W0,
               const float* __restrict__ H0, float* __restrict__ out) {
    extern __shared__ float smem[];
    // 7 SoA planes of PIXPAD floats: Wx Wy Wz Ww V0 V1 V2 (contiguous)
    float*    sP    = smem;
    float*    sWx   = sP + 0 * PIXPAD;
    float*    sWy   = sP + 1 * PIXPAD;
    float*    sWz   = sP + 2 * PIXPAD;
    float*    sWw   = sP + 3 * PIXPAD;
    float*    sV0   = sP + 4 * PIXPAD;
    float*    sV1   = sP + 5 * PIXPAD;
    float*    sV2   = sP + 6 * PIXPAD;
    unsigned* sHist = (unsigned*)(sP + 7 * PIXPAD);      // 2048 u32
    float*    sRed  = (float*)(sHist + 2048);            // NWARP*22
    float*    sB    = sRed + NWARP * 22;                 // 24
    unsigned* sSel  = (unsigned*)(sB + 24);              // 2

    const int tid  = threadIdx.x;
    const int cta  = blockIdx.x;
    const int base = cta * PIXPAD;
    const int cnt  = max(0, min(PIXPAD, NPIX - base));   // valid pixels (even)

    // ---- prologue: W0 slice + V = -log(clip(pic)); zero pads -----------------
    const float4* W0v = (const float4*)W0;
    for (int p = tid; p < PIXPAD; p += TPB) {
        float4 w = (p < cnt) ? W0v[base + p] : make_float4(0.f, 0.f, 0.f, 0.f);
        sWx[p] = w.x; sWy[p] = w.y; sWz[p] = w.z; sWw[p] = w.w;
        float v0 = 0.f, v1 = 0.f, v2 = 0.f;
        if (p < cnt) {
            float x0 = pic[0 * NPIX + base + p];
            float x1 = pic[1 * NPIX + base + p];
            float x2 = pic[2 * NPIX + base + p];
            v0 = -__logf(fminf(fmaxf(x0, 0.01f), 0.99f));
            v1 = -__logf(fminf(fmaxf(x1, 0.01f), 0.99f));
            v2 = -__logf(fminf(fmaxf(x2, 0.01f), 0.99f));
        }
        sV0[p] = v0; sV1[p] = v1; sV2[p] = v2;
    }
    ull Hdp[12];
#pragma unroll
    for (int i = 0; i < 12; ++i) { float h = H0[i]; Hdp[i] = pk(h, h); }
    __syncthreads();

    const ull* pWx = (const ull*)sWx; const ull* pWy = (const ull*)sWy;
    const ull* pWz = (const ull*)sWz; const ull* pWw = (const ull*)sWw;
    const ull* pV0 = (const ull*)sV0; const ull* pV1 = (const ull*)sV1;
    const ull* pV2 = (const ull*)sV2;
    ull* qWx = (ull*)sWx; ull* qWy = (ull*)sWy; ull* qWz = (ull*)sWz; ull* qWw = (ull*)sWw;

    unsigned nsync = 0;
    const ull epsp = pk(EPSF, EPSF);
    const int lane = tid & 31, warp = tid >> 5;

    // ---- NMF multiplicative updates: 99 full iterations -----------------------
    for (int it = 0; it < NITER - 1; ++it) {
        ull acc[22];
#pragma unroll
        for (int i = 0; i < 22; ++i) acc[i] = 0ull;

#pragma unroll
        for (int k = 0; k < KTRIPS; ++k) {
            const int i = tid + k * TPB;                 // pair index, no bounds
            ull wx = pWx[i], wy = pWy[i], wz = pWz[i], ww = pWw[i];
            ull v0 = pV0[i], v1 = pV1[i], v2 = pV2[i];

            // t_j = sum_c v_c * Hd[c,j]
            ull t0, t1, t2, t3;
            MUL2(t0, v0, Hdp[0]);  FMA2(t0, v1, Hdp[4],  t0); FMA2(t0, v2, Hdp[8],  t0);
            MUL2(t1, v0, Hdp[1]);  FMA2(t1, v1, Hdp[5],  t1); FMA2(t1, v2, Hdp[9],  t1);
            MUL2(t2, v0, Hdp[2]);  FMA2(t2, v1, Hdp[6],  t2); FMA2(t2, v2, Hdp[10], t2);
            MUL2(t3, v0, Hdp[3]);  FMA2(t3, v1, Hdp[7],  t3); FMA2(t3, v2, Hdp[11], t3);

            // u_c = Hd[c,:] . w ;  d_j = eps + sum_c Hd[c,j]*u_c  (== (w @ G)_j + eps)
            ull u0, u1, u2;
            MUL2(u0, wx, Hdp[0]); FMA2(u0, wy, Hdp[1], u0); FMA2(u0, wz, Hdp[2],  u0); FMA2(u0, ww, Hdp[3],  u0);
            MUL2(u1, wx, Hdp[4]); FMA2(u1, wy, Hdp[5], u1); FMA2(u1, wz, Hdp[6],  u1); FMA2(u1, ww, Hdp[7],  u1);
            MUL2(u2, wx, Hdp[8]); FMA2(u2, wy, Hdp[9], u2); FMA2(u2, wz, Hdp[10], u2); FMA2(u2, ww, Hdp[11], u2);
            ull d0 = epsp, d1 = epsp, d2 = epsp, d3 = epsp;
            FMA2(d0, u0, Hdp[0], d0); FMA2(d0, u1, Hdp[4], d0); FMA2(d0, u2, Hdp[8],  d0);
            FMA2(d1, u0, Hdp[1], d1); FMA2(d1, u1, Hdp[5], d1); FMA2(d1, u2, Hdp[9],  d1);
            FMA2(d2, u0, Hdp[2], d2); FMA2(d2, u1, Hdp[6], d2); FMA2(d2, u2, Hdp[10], d2);
            FMA2(d3, u0, Hdp[3], d3); FMA2(d3, u1, Hdp[7], d3); FMA2(d3, u2, Hdp[11], d3);

            // quad-paired reciprocal: one rcp2 serves all four denominators
            ull p01, p23, pq, r, q01, q23, i0, i1, i2, i3;
            MUL2(p01, d0, d1); MUL2(p23, d2, d3);
            MUL2(pq, p01, p23);
            r = rcp2(pq);                 // 2 MUFU total (vs 8)
            MUL2(q01, p23, r);            // 1/(d0*d1)
            MUL2(q23, p01, r);            // 1/(d2*d3)
            MUL2(i0, d1, q01); MUL2(i1, d0, q01);
            MUL2(i2, d3, q23); MUL2(i3, d2, q23);

            // n_j = (w_j * t_j) * inv_j
            ull n0, n1, n2, n3;
            MUL2(n0, wx, t0); MUL2(n1, wy, t1); MUL2(n2, wz, t2); MUL2(n3, ww, t3);
            MUL2(n0, n0, i0); MUL2(n1, n1, i1); MUL2(n2, n2, i2); MUL2(n3, n3, i3);
            qWx[i] = n0; qWy[i] = n1; qWz[i] = n2; qWw[i] = n3;

            // S1 = V @ Wc_new (3x4)
            FMA2(acc[0],  v0, n0, acc[0]);  FMA2(acc[1],  v0, n1, acc[1]);
            FMA2(acc[2],  v0, n2, acc[2]);  FMA2(acc[3],  v0, n3, acc[3]);
            FMA2(acc[4],  v1, n0, acc[4]);  FMA2(acc[5],  v1, n1, acc[5]);
            FMA2(acc[6],  v1, n2, acc[6]);  FMA2(acc[7],  v1, n3, acc[7]);
            FMA2(acc[8],  v2, n0, acc[8]);  FMA2(acc[9],  v2, n1, acc[9]);
            FMA2(acc[10], v2, n2, acc[10]); FMA2(acc[11], v2, n3, acc[11]);
            // S2 = Wc_new^T Wc_new (10 uniques)
            FMA2(acc[12], n0, n0, acc[12]); FMA2(acc[13], n0, n1, acc[13]);
            FMA2(acc[14], n0, n2, acc[14]); FMA2(acc[15], n0, n3, acc[15]);
            FMA2(acc[16], n1, n1, acc[16]); FMA2(acc[17], n1, n2, acc[17]);
            FMA2(acc[18], n1, n3, acc[18]); FMA2(acc[19], n2, n2, acc[19]);
            FMA2(acc[20], n2, n3, acc[20]); FMA2(acc[21], n3, n3, acc[21]);
        }

        // fold packed halves; block reduce 22 accumulators
        float accs[22];
#pragma unroll
        for (int i = 0; i < 22; ++i) { float a, b; upk(acc[i], a, b); accs[i] = a + b; }
#pragma unroll
        for (int i = 0; i < 22; ++i) {
            float v = accs[i];
#pragma unroll
            for (int off = 16; off > 0; off >>= 1) v += __shfl_down_sync(0xffffffffu, v, off);
            accs[i] = v;
        }
        if (lane == 0) {
#pragma unroll
            for (int i = 0; i < 22; ++i) sRed[warp * 22 + i] = accs[i];
        }
        __syncthreads();
        const int par = it & 1;
        if (tid < 22) {
            float s = 0.f;
#pragma unroll
            for (int w = 0; w < NWARP; ++w) s += sRed[w * 22 + tid];
            g_part[par][tid * 160 + cta] = s;
        }
        gsync(cta, ++nsync);

        // parallel cross-CTA reduce: warp per value (16 warps, 22 values, 2 waves)
        for (int v = warp; v < 22; v += NWARP) {
            float s = 0.f;
#pragma unroll
            for (int c = lane; c < NCTA; c += 32) s += __ldcg(&g_part[par][v * 160 + c]);
#pragma unroll
            for (int off = 16; off > 0; off >>= 1) s += __shfl_down_sync(0xffffffffu, s, off);
            if (lane == 0) sB[v] = s;
        }
        __syncthreads();

        // Hd update (redundant, deterministic in every thread)
        float hd[12];
#pragma unroll
        for (int i = 0; i < 12; ++i) { float a, b; upk(Hdp[i], a, b); hd[i] = a; }
        float S2[16];
        {
            float p00 = sB[12], p01 = sB[13], p02 = sB[14], p03 = sB[15];
            float p11 = sB[16], p12 = sB[17], p13 = sB[18];
            float p22 = sB[19], p23 = sB[20], p33 = sB[21];
            S2[0]=p00; S2[1]=p01; S2[2]=p02; S2[3]=p03;
            S2[4]=p01; S2[5]=p11; S2[6]=p12; S2[7]=p13;
            S2[8]=p02; S2[9]=p12; S2[10]=p22; S2[11]=p23;
            S2[12]=p03; S2[13]=p13; S2[14]=p23; S2[15]=p33;
        }
#pragma unroll
        for (int c = 0; c < 3; ++c)
#pragma unroll
            for (int j = 0; j < 4; ++j) {
                float den = hd[c*4+0]*S2[0*4+j] + hd[c*4+1]*S2[1*4+j]
                          + hd[c*4+2]*S2[2*4+j] + hd[c*4+3]*S2[3*4+j] + EPSF;
                float hn = hd[c*4+j] * sB[c*4+j] * frcp(den);
                Hdp[c*4+j] = pk(hn, hn);
            }
    }

    // ---- final iteration: Wc update only (sums + Hd update are dead work) -----
#pragma unroll
    for (int k = 0; k < KTRIPS; ++k) {
        const int i = tid + k * TPB;
        ull wx = pWx[i], wy = pWy[i], wz = pWz[i], ww = pWw[i];
        ull v0 = pV0[i], v1 = pV1[i], v2 = pV2[i];
        ull t0, t1, t2, t3;
        MUL2(t0, v0, Hdp[0]);  FMA2(t0, v1, Hdp[4],  t0); FMA2(t0, v2, Hdp[8],  t0);
        MUL2(t1, v0, Hdp[1]);  FMA2(t1, v1, Hdp[5],  t1); FMA2(t1, v2, Hdp[9],  t1);
        MUL2(t2, v0, Hdp[2]);  FMA2(t2, v1, Hdp[6],  t2); FMA2(t2, v2, Hdp[10], t2);
        MUL2(t3, v0, Hdp[3]);  FMA2(t3, v1, Hdp[7],  t3); FMA2(t3, v2, Hdp[11], t3);
        ull u0, u1, u2;
        MUL2(u0, wx, Hdp[0]); FMA2(u0, wy, Hdp[1], u0); FMA2(u0, wz, Hdp[2],  u0); FMA2(u0, ww, Hdp[3],  u0);
        MUL2(u1, wx, Hdp[4]); FMA2(u1, wy, Hdp[5], u1); FMA2(u1, wz, Hdp[6],  u1); FMA2(u1, ww, Hdp[7],  u1);
        MUL2(u2, wx, Hdp[8]); FMA2(u2, wy, Hdp[9], u2); FMA2(u2, wz, Hdp[10], u2); FMA2(u2, ww, Hdp[11], u2);
        ull d0 = epsp, d1 = epsp, d2 = epsp, d3 = epsp;
        FMA2(d0, u0, Hdp[0], d0); FMA2(d0, u1, Hdp[4], d0); FMA2(d0, u2, Hdp[8],  d0);
        FMA2(d1, u0, Hdp[1], d1); FMA2(d1, u1, Hdp[5], d1); FMA2(d1, u2, Hdp[9],  d1);
        FMA2(d2, u0, Hdp[2], d2); FMA2(d2, u1, Hdp[6], d2); FMA2(d2, u2, Hdp[10], d2);
        FMA2(d3, u0, Hdp[3], d3); FMA2(d3, u1, Hdp[7], d3); FMA2(d3, u2, Hdp[11], d3);
        ull p01, p23, pq, r, q01, q23, i0, i1, i2, i3;
        MUL2(p01, d0, d1); MUL2(p23, d2, d3);
        MUL2(pq, p01, p23);
        r = rcp2(pq);
        MUL2(q01, p23, r); MUL2(q23, p01, r);
        MUL2(i0, d1, q01); MUL2(i1, d0, q01);
        MUL2(i2, d3, q23); MUL2(i3, d2, q23);
        ull n0, n1, n2, n3;
        MUL2(n0, wx, t0); MUL2(n1, wy, t1); MUL2(n2, wz, t2); MUL2(n3, ww, t3);
        MUL2(n0, n0, i0); MUL2(n1, n1, i1); MUL2(n2, n2, i2); MUL2(n3, n3, i3);
        qWx[i] = n0; qWy[i] = n1; qWz[i] = n2; qWw[i] = n3;
    }
    __syncthreads();

    // ---- global 0.99-quantile: 3-round radix select ---------------------------
    float pos = 0.99f * (float)(4 * NPIX - 1);
    unsigned lo = (unsigned)pos;
    float fr = pos - (float)lo;
    unsigned rank = lo + (fr > 0.5f ? 1u : 0u);
    rank += (unsigned)(4 * (NCTA * PIXPAD - NPIX));      // pad zeros sit below quantile

    const int tot = 4 * PIXPAD;                          // the 4 W planes, no bounds
    unsigned b0, b1, b2;

    // round 0: bits [31:21]
    for (int i = tid; i < 2048; i += TPB) sHist[i] = 0u;
    __syncthreads();
    for (int i = tid; i < tot; i += TPB) {
        unsigned k = __float_as_uint(sP[i]);
        hist_add(sHist, k >> 21, true);
    }
    __syncthreads();
    for (int i = tid; i < 2048; i += TPB) { unsigned h = sHist[i]; if (h) atomicAdd(&g_h0[i], h); }
    gsync(cta, ++nsync);
    if (tid < 32) find_bin(g_h0, 2048, rank, sSel);
    __syncthreads();
    b0 = sSel[0]; rank -= sSel[1];

    // round 1: bits [20:10]
    for (int i = tid; i < 2048; i += TPB) sHist[i] = 0u;
    __syncthreads();
    for (int i = tid; i < tot; i += TPB) {
        unsigned k = __float_as_uint(sP[i]);
        hist_add(sHist, (k >> 10) & 2047u, (k >> 21) == b0);
    }
    __syncthreads();
    for (int i = tid; i < 2048; i += TPB) { unsigned h = sHist[i]; if (h) atomicAdd(&g_h1[i], h); }
    gsync(cta, ++nsync);
    if (tid < 32) find_bin(g_h1, 2048, rank, sSel);
    __syncthreads();
    b1 = sSel[0]; rank -= sSel[1];

    // round 2: bits [9:0]
    for (int i = tid; i < 1024; i += TPB) sHist[i] = 0u;
    __syncthreads();
    unsigned pref = (b0 << 11) | b1;
    for (int i = tid; i < tot; i += TPB) {
        unsigned k = __float_as_uint(sP[i]);
        hist_add(sHist, k & 1023u, (k >> 10) == pref);
    }
    __syncthreads();
    for (int i = tid; i < 1024; i += TPB) { unsigned h = sHist[i]; if (h) atomicAdd(&g_h2[i], h); }
    gsync(cta, ++nsync);
    if (tid < 32) find_bin(g_h2, 1024, rank, sSel);
    __syncthreads();
    b2 = sSel[0];

    float qv = __uint_as_float((b0 << 21) | (b1 << 10) | b2);

    // ---- epilogue: out = clip(exp(-(W_target @ (Wc^T * Ht/q))), 0, 1) ---------
    float s = HtRM[0] * frcp(qv);
    float w0 = Wt[0]*s,  w1 = Wt[1]*s,  w2 = Wt[2]*s,  w3 = Wt[3]*s;
    float w4 = Wt[4]*s,  w5 = Wt[5]*s,  w6 = Wt[6]*s,  w7 = Wt[7]*s;
    float w8 = Wt[8]*s,  w9 = Wt[9]*s,  wA = Wt[10]*s, wB = Wt[11]*s;
    for (int p = tid; p < cnt; p += TPB) {
        float x = sWx[p], y = sWy[p], z = sWz[p], w = sWw[p];
        float a0 = w0*x + w1*y + w2*z + w3*w;
        float a1 = w4*x + w5*y + w6*z + w7*w;
        float a2 = w8*x + w9*y + wA*z + wB*w;
        out[0*NPIX + base + p] = __saturatef(__expf(-a0));
        out[1*NPIX + base + p] = __saturatef(__expf(-a1));
        out[2*NPIX + base + p] = __saturatef(__expf(-a2));
    }
}

// ---------------- launch -------------------------------------------------------
extern "C" void kernel_launch(void* const* d_in, const int* in_sizes, int n_in,
                              void* d_out, int out_size) {
    const float *pic = nullptr, *Wt = nullptr, *Htq = nullptr, *W0 = nullptr, *H0 = nullptr;
    for (int i = 0; i < n_in; ++i) {
        int sz = in_sizes[i];
        if      (sz == 3 * NPIX) pic = (const float*)d_in[i];
        else if (sz == 4 * NPIX) W0  = (const float*)d_in[i];
        else if (sz == 1)        Htq = (const float*)d_in[i];
        else if (sz == 12) { if (!Wt) Wt = (const float*)d_in[i]; else H0 = (const float*)d_in[i]; }
    }
    float* out = (float*)d_out;

    const size_t smem_bytes =
        (size_t)7 * PIXPAD * 4 +      // 7 SoA planes (200704)
        2048 * 4 +                    // sHist
        NWARP * 22 * 4 +              // sRed
        24 * 4 + 2 * 4 + 64;          // sB + sSel + pad

    cudaFuncSetAttribute(he_norm_kernel, cudaFuncAttributeMaxDynamicSharedMemorySize,
                         (int)smem_bytes);

    hx_init<<<4, 512>>>();
    he_norm_kernel<<<NCTA, TPB, smem_bytes>>>(pic, Wt, Htq, W0, H0, out);
}

// round 16
// speedup vs baseline: 1.0700x; 1.0700x over previous
#include <cuda_runtime.h>

#define NPIX   (1024*1024)
#define TPB    384
#define NWARP  (TPB/32)              // 12
#define NCTA   148
#define PIXPAD 7680                  // = 2 * 10 * TPB exactly; >= 7086
#define NPAIRS (PIXPAD/2)            // 3840 = 10*TPB -> fixed trip count 10
#define KTRIPS 10
#define EPSF   1e-8f
#define NITER  100

typedef unsigned long long ull;

// ---------------- packed f32x2 helpers --------------------------------------
#define FMA2(d,a,b,c) asm("fma.rn.f32x2 %0, %1, %2, %3;" : "=l"(d) : "l"(a), "l"(b), "l"(c))
#define MUL2(d,a,b)   asm("mul.rn.f32x2 %0, %1, %2;"     : "=l"(d) : "l"(a), "l"(b))

__device__ __forceinline__ ull pk(float lo, float hi) {
    ull r; asm("mov.b64 %0, {%1,%2};" : "=l"(r) : "f"(lo), "f"(hi)); return r;
}
__device__ __forceinline__ void upk(ull v, float& lo, float& hi) {
    asm("mov.b64 {%0,%1}, %2;" : "=f"(lo), "=f"(hi) : "l"(v));
}
__device__ __forceinline__ float frcp(float x) {
    float r; asm("rcp.approx.f32 %0, %1;" : "=f"(r) : "f"(x)); return r;
}
__device__ __forceinline__ ull rcp2(ull v) {
    float a, b; upk(v, a, b); return pk(frcp(a), frcp(b));
}

// ---------------- device globals (scratch; zeroed each launch by hx_init) ---
__device__ unsigned g_bar;
__device__ unsigned g_h0[2048];
__device__ unsigned g_h1[2048];
__device__ unsigned g_h2[1024];
__device__ float    g_part[2][22 * 160];

__global__ void hx_init() {
    int t = blockIdx.x * blockDim.x + threadIdx.x;
    if (t == 0) g_bar = 0u;
    if (t < 2048) { g_h0[t] = 0u; g_h1[t] = 0u; }
    if (t < 1024) g_h2[t] = 0u;
}

// ---------------- software grid barrier (148 co-resident CTAs) ---------------
// R10's single-counter atomic+spin: measured fastest across 5 barrier designs.
__device__ __forceinline__ void gsync(unsigned target) {
    __syncthreads();
    if (threadIdx.x == 0) {
        __threadfence();
        atomicAdd(&g_bar, 1u);
        while (*(volatile unsigned*)&g_bar < target) { }
        __threadfence();
    }
    __syncthreads();
}

// ---------------- warp-0 bin search for radix select -------------------------
__device__ __forceinline__ void find_bin(const unsigned* hist, int nb, unsigned r,
                                         unsigned* sel_out) {
    int lane = threadIdx.x & 31;
    int ch = nb >> 5;
    unsigned csum = 0;
    for (int i = 0; i < ch; ++i) csum += __ldcg(&hist[lane * ch + i]);
    unsigned inc = csum;
#pragma unroll
    for (int off = 1; off < 32; off <<= 1) {
        unsigned t = __shfl_up_sync(0xffffffffu, inc, off);
        if (lane >= off) inc += t;
    }
    unsigned excl = inc - csum;
    bool has = (r >= excl) && (r < inc);
    unsigned m = __ballot_sync(0xffffffffu, has);
    int sel = __ffs(m) - 1;
    unsigned bin = 0, before = 0;
    if (lane == sel) {
        unsigned c = excl;
        for (int i = 0; i < ch; ++i) {
            unsigned h = __ldcg(&hist[sel * ch + i]);
            if (r < c + h) { bin = (unsigned)(sel * ch + i); before = c; break; }
            c += h;
        }
    }
    bin    = __shfl_sync(0xffffffffu, bin, sel);
    before = __shfl_sync(0xffffffffu, before, sel);
    if (lane == 0) { sel_out[0] = bin; sel_out[1] = before; }
}

// warp-aggregated histogram add (all 32 lanes participate)
__device__ __forceinline__ void hist_add(unsigned* sHist, unsigned bin, bool active) {
    unsigned key = active ? bin : 0xffffffffu;
    unsigned mask = __match_any_sync(0xffffffffu, key);
    int leader = __ffs(mask) - 1;
    if (active && (int)(threadIdx.x & 31) == leader)
        atomicAdd(&sHist[bin], (unsigned)__popc(mask));
}

// ---------------- the persistent kernel --------------------------------------
__global__ void __launch_bounds__(TPB, 1)
he_norm_kernel(const float* __restrict__ pic, const float* __restrict__ Wt,
               const float* __restrict__ HtRM, const float* __restrict__ W0,
               const float* __restrict__ H0, float* __restrict__ out) {
    extern __shared__ float smem[];
    // 7 SoA planes of PIXPAD floats: Wx Wy Wz Ww V0 V1 V2 (contiguous)
    float*    sP    = smem;
    float*    sWx   = sP + 0 * PIXPAD;
    float*    sWy   = sP + 1 * PIXPAD;
    float*    sWz   = sP + 2 * PIXPAD;
    float*    sWw   = sP + 3 * PIXPAD;
    float*    sV0   = sP + 4 * PIXPAD;
    float*    sV1   = sP + 5 * PIXPAD;
    float*    sV2   = sP + 6 * PIXPAD;
    unsigned* sHist = (unsigned*)(sP + 7 * PIXPAD);      // 2048 u32
    float*    sRed  = (float*)(sHist + 2048);            // NWARP*22
    float*    sB    = sRed + NWARP * 22;                 // 24
    unsigned* sSel  = (unsigned*)(sB + 24);              // 2

    const int tid  = threadIdx.x;
    const int cta  = blockIdx.x;
    const int base = cta * PIXPAD;
    const int cnt  = max(0, min(PIXPAD, NPIX - base));   // valid pixels (even)

    // ---- prologue: W0 slice + V = -log(clip(pic)); zero pads -----------------
    const float4* W0v = (const float4*)W0;
    for (int p = tid; p < PIXPAD; p += TPB) {
        float4 w = (p < cnt) ? W0v[base + p] : make_float4(0.f, 0.f, 0.f, 0.f);
        sWx[p] = w.x; sWy[p] = w.y; sWz[p] = w.z; sWw[p] = w.w;
        float v0 = 0.f, v1 = 0.f, v2 = 0.f;
        if (p < cnt) {
            float x0 = pic[0 * NPIX + base + p];
            float x1 = pic[1 * NPIX + base + p];
            float x2 = pic[2 * NPIX + base + p];
            v0 = -__logf(fminf(fmaxf(x0, 0.01f), 0.99f));
            v1 = -__logf(fminf(fmaxf(x1, 0.01f), 0.99f));
            v2 = -__logf(fminf(fmaxf(x2, 0.01f), 0.99f));
        }
        sV0[p] = v0; sV1[p] = v1; sV2[p] = v2;
    }
    ull Hdp[12];
#pragma unroll
    for (int i = 0; i < 12; ++i) { float h = H0[i]; Hdp[i] = pk(h, h); }
    __syncthreads();

    const ull* pWx = (const ull*)sWx; const ull* pWy = (const ull*)sWy;
    const ull* pWz = (const ull*)sWz; const ull* pWw = (const ull*)sWw;
    const ull* pV0 = (const ull*)sV0; const ull* pV1 = (const ull*)sV1;
    const ull* pV2 = (const ull*)sV2;
    ull* qWx = (ull*)sWx; ull* qWy = (ull*)sWy; ull* qWz = (ull*)sWz; ull* qWw = (ull*)sWw;

    unsigned nsync = 0;
    const ull epsp = pk(EPSF, EPSF);
    const int lane = tid & 31, warp = tid >> 5;

    // ---- NMF multiplicative updates: 99 full iterations -----------------------
    for (int it = 0; it < NITER - 1; ++it) {
        ull acc[22];
#pragma unroll
        for (int i = 0; i < 22; ++i) acc[i] = 0ull;

#pragma unroll
        for (int k = 0; k < KTRIPS; ++k) {
            const int i = tid + k * TPB;                 // pair index, no bounds
            ull wx = pWx[i], wy = pWy[i], wz = pWz[i], ww = pWw[i];
            ull v0 = pV0[i], v1 = pV1[i], v2 = pV2[i];

            // t_j = sum_c v_c * Hd[c,j]
            ull t0, t1, t2, t3;
            MUL2(t0, v0, Hdp[0]);  FMA2(t0, v1, Hdp[4],  t0); FMA2(t0, v2, Hdp[8],  t0);
            MUL2(t1, v0, Hdp[1]);  FMA2(t1, v1, Hdp[5],  t1); FMA2(t1, v2, Hdp[9],  t1);
            MUL2(t2, v0, Hdp[2]);  FMA2(t2, v1, Hdp[6],  t2); FMA2(t2, v2, Hdp[10], t2);
            MUL2(t3, v0, Hdp[3]);  FMA2(t3, v1, Hdp[7],  t3); FMA2(t3, v2, Hdp[11], t3);

            // u_c = Hd[c,:] . w ;  d_j = eps + sum_c Hd[c,j]*u_c  (== (w @ G)_j + eps)
            ull u0, u1, u2;
            MUL2(u0, wx, Hdp[0]); FMA2(u0, wy, Hdp[1], u0); FMA2(u0, wz, Hdp[2],  u0); FMA2(u0, ww, Hdp[3],  u0);
            MUL2(u1, wx, Hdp[4]); FMA2(u1, wy, Hdp[5], u1); FMA2(u1, wz, Hdp[6],  u1); FMA2(u1, ww, Hdp[7],  u1);
            MUL2(u2, wx, Hdp[8]); FMA2(u2, wy, Hdp[9], u2); FMA2(u2, wz, Hdp[10], u2); FMA2(u2, ww, Hdp[11], u2);
            ull d0 = epsp, d1 = epsp, d2 = epsp, d3 = epsp;
            FMA2(d0, u0, Hdp[0], d0); FMA2(d0, u1, Hdp[4], d0); FMA2(d0, u2, Hdp[8],  d0);
            FMA2(d1, u0, Hdp[1], d1); FMA2(d1, u1, Hdp[5], d1); FMA2(d1, u2, Hdp[9],  d1);
            FMA2(d2, u0, Hdp[2], d2); FMA2(d2, u1, Hdp[6], d2); FMA2(d2, u2, Hdp[10], d2);
            FMA2(d3, u0, Hdp[3], d3); FMA2(d3, u1, Hdp[7], d3); FMA2(d3, u2, Hdp[11], d3);

            // quad-paired reciprocal: one rcp2 serves all four denominators
            ull p01, p23, pq, r, q01, q23, i0, i1, i2, i3;
            MUL2(p01, d0, d1); MUL2(p23, d2, d3);
            MUL2(pq, p01, p23);
            r = rcp2(pq);                 // 2 MUFU total (vs 8)
            MUL2(q01, p23, r);            // 1/(d0*d1)
            MUL2(q23, p01, r);            // 1/(d2*d3)
            MUL2(i0, d1, q01); MUL2(i1, d0, q01);
            MUL2(i2, d3, q23); MUL2(i3, d2, q23);

            // n_j = (w_j * t_j) * inv_j
            ull n0, n1, n2, n3;
            MUL2(n0, wx, t0); MUL2(n1, wy, t1); MUL2(n2, wz, t2); MUL2(n3, ww, t3);
            MUL2(n0, n0, i0); MUL2(n1, n1, i1); MUL2(n2, n2, i2); MUL2(n3, n3, i3);
            qWx[i] = n0; qWy[i] = n1; qWz[i] = n2; qWw[i] = n3;

            // S1 = V @ Wc_new (3x4)
            FMA2(acc[0],  v0, n0, acc[0]);  FMA2(acc[1],  v0, n1, acc[1]);
            FMA2(acc[2],  v0, n2, acc[2]);  FMA2(acc[3],  v0, n3, acc[3]);
            FMA2(acc[4],  v1, n0, acc[4]);  FMA2(acc[5],  v1, n1, acc[5]);
            FMA2(acc[6],  v1, n2, acc[6]);  FMA2(acc[7],  v1, n3, acc[7]);
            FMA2(acc[8],  v2, n0, acc[8]);  FMA2(acc[9],  v2, n1, acc[9]);
            FMA2(acc[10], v2, n2, acc[10]); FMA2(acc[11], v2, n3, acc[11]);
            // S2 = Wc_new^T Wc_new (10 uniques)
            FMA2(acc[12], n0, n0, acc[12]); FMA2(acc[13], n0, n1, acc[13]);
            FMA2(acc[14], n0, n2, acc[14]); FMA2(acc[15], n0, n3, acc[15]);
            FMA2(acc[16], n1, n1, acc[16]); FMA2(acc[17], n1, n2, acc[17]);
            FMA2(acc[18], n1, n3, acc[18]); FMA2(acc[19], n2, n2, acc[19]);
            FMA2(acc[20], n2, n3, acc[20]); FMA2(acc[21], n3, n3, acc[21]);
        }

        // fold packed halves; block reduce 22 accumulators
        float accs[22];
#pragma unroll
        for (int i = 0; i < 22; ++i) { float a, b; upk(acc[i], a, b); accs[i] = a + b; }
#pragma unroll
        for (int i = 0; i < 22; ++i) {
            float v = accs[i];
#pragma unroll
            for (int off = 16; off > 0; off >>= 1) v += __shfl_down_sync(0xffffffffu, v, off);
            accs[i] = v;
        }
        if (lane == 0) {
#pragma unroll
            for (int i = 0; i < 22; ++i) sRed[warp * 22 + i] = accs[i];
        }
        __syncthreads();
        const int par = it & 1;
        if (tid < 22) {
            float s = 0.f;
#pragma unroll
            for (int w = 0; w < NWARP; ++w) s += sRed[w * 22 + tid];
            g_part[par][tid * 160 + cta] = s;
        }
        gsync(++nsync * NCTA);

        // parallel cross-CTA reduce: warp per value (12 warps, 22 values, 2 waves)
        for (int v = warp; v < 22; v += NWARP) {
            float s = 0.f;
#pragma unroll
            for (int c = lane; c < NCTA; c += 32) s += __ldcg(&g_part[par][v * 160 + c]);
#pragma unroll
            for (int off = 16; off > 0; off >>= 1) s += __shfl_down_sync(0xffffffffu, s, off);
            if (lane == 0) sB[v] = s;
        }
        __syncthreads();

        // Hd update (redundant, deterministic in every thread)
        float hd[12];
#pragma unroll
        for (int i = 0; i < 12; ++i) { float a, b; upk(Hdp[i], a, b); hd[i] = a; }
        float S2[16];
        {
            float p00 = sB[12], p01 = sB[13], p02 = sB[14], p03 = sB[15];
            float p11 = sB[16], p12 = sB[17], p13 = sB[18];
            float p22 = sB[19], p23 = sB[20], p33 = sB[21];
            S2[0]=p00; S2[1]=p01; S2[2]=p02; S2[3]=p03;
            S2[4]=p01; S2[5]=p11; S2[6]=p12; S2[7]=p13;
            S2[8]=p02; S2[9]=p12; S2[10]=p22; S2[11]=p23;
            S2[12]=p03; S2[13]=p13; S2[14]=p23; S2[15]=p33;
        }
#pragma unroll
        for (int c = 0; c < 3; ++c)
#pragma unroll
            for (int j = 0; j < 4; ++j) {
                float den = hd[c*4+0]*S2[0*4+j] + hd[c*4+1]*S2[1*4+j]
                          + hd[c*4+2]*S2[2*4+j] + hd[c*4+3]*S2[3*4+j] + EPSF;
                float hn = hd[c*4+j] * sB[c*4+j] * frcp(den);
                Hdp[c*4+j] = pk(hn, hn);
            }
    }

    // ---- final iteration: Wc update only (sums + Hd update are dead work) -----
#pragma unroll
    for (int k = 0; k < KTRIPS; ++k) {
        const int i = tid + k * TPB;
        ull wx = pWx[i], wy = pWy[i], wz = pWz[i], ww = pWw[i];
        ull v0 = pV0[i], v1 = pV1[i], v2 = pV2[i];
        ull t0, t1, t2, t3;
        MUL2(t0, v0, Hdp[0]);  FMA2(t0, v1, Hdp[4],  t0); FMA2(t0, v2, Hdp[8],  t0);
        MUL2(t1, v0, Hdp[1]);  FMA2(t1, v1, Hdp[5],  t1); FMA2(t1, v2, Hdp[9],  t1);
        MUL2(t2, v0, Hdp[2]);  FMA2(t2, v1, Hdp[6],  t2); FMA2(t2, v2, Hdp[10], t2);
        MUL2(t3, v0, Hdp[3]);  FMA2(t3, v1, Hdp[7],  t3); FMA2(t3, v2, Hdp[11], t3);
        ull u0, u1, u2;
        MUL2(u0, wx, Hdp[0]); FMA2(u0, wy, Hdp[1], u0); FMA2(u0, wz, Hdp[2],  u0); FMA2(u0, ww, Hdp[3],  u0);
        MUL2(u1, wx, Hdp[4]); FMA2(u1, wy, Hdp[5], u1); FMA2(u1, wz, Hdp[6],  u1); FMA2(u1, ww, Hdp[7],  u1);
        MUL2(u2, wx, Hdp[8]); FMA2(u2, wy, Hdp[9], u2); FMA2(u2, wz, Hdp[10], u2); FMA2(u2, ww, Hdp[11], u2);
        ull d0 = epsp, d1 = epsp, d2 = epsp, d3 = epsp;
        FMA2(d0, u0, Hdp[0], d0); FMA2(d0, u1, Hdp[4], d0); FMA2(d0, u2, Hdp[8],  d0);
        FMA2(d1, u0, Hdp[1], d1); FMA2(d1, u1, Hdp[5], d1); FMA2(d1, u2, Hdp[9],  d1);
        FMA2(d2, u0, Hdp[2], d2); FMA2(d2, u1, Hdp[6], d2); FMA2(d2, u2, Hdp[10], d2);
        FMA2(d3, u0, Hdp[3], d3); FMA2(d3, u1, Hdp[7], d3); FMA2(d3, u2, Hdp[11], d3);
        ull p01, p23, pq, r, q01, q23, i0, i1, i2, i3;
        MUL2(p01, d0, d1); MUL2(p23, d2, d3);
        MUL2(pq, p01, p23);
        r = rcp2(pq);
        MUL2(q01, p23, r); MUL2(q23, p01, r);
        MUL2(i0, d1, q01); MUL2(i1, d0, q01);
        MUL2(i2, d3, q23); MUL2(i3, d2, q23);
        ull n0, n1, n2, n3;
        MUL2(n0, wx, t0); MUL2(n1, wy, t1); MUL2(n2, wz, t2); MUL2(n3, ww, t3);
        MUL2(n0, n0, i0); MUL2(n1, n1, i1); MUL2(n2, n2, i2); MUL2(n3, n3, i3);
        qWx[i] = n0; qWy[i] = n1; qWz[i] = n2; qWw[i] = n3;
    }
    __syncthreads();

    // ---- global 0.99-quantile: 3-round radix select ---------------------------
    float pos = 0.99f * (float)(4 * NPIX - 1);
    unsigned lo = (unsigned)pos;
    float fr = pos - (float)lo;
    unsigned rank = lo + (fr > 0.5f ? 1u : 0u);
    rank += (unsigned)(4 * (NCTA * PIXPAD - NPIX));      // pad zeros sit below quantile

    const int tot = 4 * PIXPAD;                          // the 4 W planes, no bounds
    unsigned b0, b1, b2;

    // round 0: bits [31:21]
    for (int i = tid; i < 2048; i += TPB) sHist[i] = 0u;
    __syncthreads();
    for (int i = tid; i < tot; i += TPB) {
        unsigned k = __float_as_uint(sP[i]);
        hist_add(sHist, k >> 21, true);
    }
    __syncthreads();
    for (int i = tid; i < 2048; i += TPB) { unsigned h = sHist[i]; if (h) atomicAdd(&g_h0[i], h); }
    gsync(++nsync * NCTA);
    if (tid < 32) find_bin(g_h0, 2048, rank, sSel);
    __syncthreads();
    b0 = sSel[0]; rank -= sSel[1];

    // round 1: bits [20:10]
    for (int i = tid; i < 2048; i += TPB) sHist[i] = 0u;
    __syncthreads();
    for (int i = tid; i < tot; i += TPB) {
        unsigned k = __float_as_uint(sP[i]);
        hist_add(sHist, (k >> 10) & 2047u, (k >> 21) == b0);
    }
    __syncthreads();
    for (int i = tid; i < 2048; i += TPB) { unsigned h = sHist[i]; if (h) atomicAdd(&g_h1[i], h); }
    gsync(++nsync * NCTA);
    if (tid < 32) find_bin(g_h1, 2048, rank, sSel);
    __syncthreads();
    b1 = sSel[0]; rank -= sSel[1];

    // round 2: bits [9:0]
    for (int i = tid; i < 1024; i += TPB) sHist[i] = 0u;
    __syncthreads();
    unsigned pref = (b0 << 11) | b1;
    for (int i = tid; i < tot; i += TPB) {
        unsigned k = __float_as_uint(sP[i]);
        hist_add(sHist, k & 1023u, (k >> 10) == pref);
    }
    __syncthreads();
    for (int i = tid; i < 1024; i += TPB) { unsigned h = sHist[i]; if (h) atomicAdd(&g_h2[i], h); }
    gsync(++nsync * NCTA);
    if (tid < 32) find_bin(g_h2, 1024, rank, sSel);
    __syncthreads();
    b2 = sSel[0];

    float qv = __uint_as_float((b0 << 21) | (b1 << 10) | b2);

    // ---- epilogue: out = clip(exp(-(W_target @ (Wc^T * Ht/q))), 0, 1) ---------
    float s = HtRM[0] * frcp(qv);
    float w0 = Wt[0]*s,  w1 = Wt[1]*s,  w2 = Wt[2]*s,  w3 = Wt[3]*s;
    float w4 = Wt[4]*s,  w5 = Wt[5]*s,  w6 = Wt[6]*s,  w7 = Wt[7]*s;
    float w8 = Wt[8]*s,  w9 = Wt[9]*s,  wA = Wt[10]*s, wB = Wt[11]*s;
    for (int p = tid; p < cnt; p += TPB) {
        float x = sWx[p], y = sWy[p], z = sWz[p], w = sWw[p];
        float a0 = w0*x + w1*y + w2*z + w3*w;
        float a1 = w4*x + w5*y + w6*z + w7*w;
        float a2 = w8*x + w9*y + wA*z + wB*w;
        out[0*NPIX + base + p] = __saturatef(__expf(-a0));
        out[1*NPIX + base + p] = __saturatef(__expf(-a1));
        out[2*NPIX + base + p] = __saturatef(__expf(-a2));
    }
}

// ---------------- launch -------------------------------------------------------
extern "C" void kernel_launch(void* const* d_in, const int* in_sizes, int n_in,
                              void* d_out, int out_size) {
    const float *pic = nullptr, *Wt = nullptr, *Htq = nullptr, *W0 = nullptr, *H0 = nullptr;
    for (int i = 0; i < n_in; ++i) {
        int sz = in_sizes[i];
        if      (sz == 3 * NPIX) pic = (const float*)d_in[i];
        else if (sz == 4 * NPIX) W0  = (const float*)d_in[i];
        else if (sz == 1)        Htq = (const float*)d_in[i];
        else if (sz == 12) { if (!Wt) Wt = (const float*)d_in[i]; else H0 = (const float*)d_in[i]; }
    }
    float* out = (float*)d_out;

    const size_t smem_bytes =
        (size_t)7 * PIXPAD * 4 +      // 7 SoA planes (215040)
        2048 * 4 +                    // sHist
        NWARP * 22 * 4 +              // sRed
        24 * 4 + 2 * 4 + 64;          // sB + sSel + pad

    cudaFuncSetAttribute(he_norm_kernel, cudaFuncAttributeMaxDynamicSharedMemorySize,
                         (int)smem_bytes);

    hx_init<<<4, 512>>>();
    he_norm_kernel<<<NCTA, TPB, smem_bytes>>>(pic, Wt, Htq, W0, H0, out);
}

// round 17
// speedup vs baseline: 1.1398x; 1.0652x over previous
#include <cuda_runtime.h>

#define NPIX   (1024*1024)
#define TPB    512
#define NWARP  (TPB/32)              // 16
#define NCTA   148
#define PIXPAD 7168                  // = 2 * 7 * TPB exactly
#define NPAIRS (PIXPAD/2)            // 3584 = 7*TPB -> fixed trip count 7
#define KTRIPS 7
#define EPSF   1e-8f
#define NITER  100

typedef unsigned long long ull;

// ---------------- packed f32x2 helpers --------------------------------------
#define FMA2(d,a,b,c) asm("fma.rn.f32x2 %0, %1, %2, %3;" : "=l"(d) : "l"(a), "l"(b), "l"(c))
#define MUL2(d,a,b)   asm("mul.rn.f32x2 %0, %1, %2;"     : "=l"(d) : "l"(a), "l"(b))

__device__ __forceinline__ ull pk(float lo, float hi) {
    ull r; asm("mov.b64 %0, {%1,%2};" : "=l"(r) : "f"(lo), "f"(hi)); return r;
}
__device__ __forceinline__ void upk(ull v, float& lo, float& hi) {
    asm("mov.b64 {%0,%1}, %2;" : "=f"(lo), "=f"(hi) : "l"(v));
}
__device__ __forceinline__ float frcp(float x) {
    float r; asm("rcp.approx.f32 %0, %1;" : "=f"(r) : "f"(x)); return r;
}
__device__ __forceinline__ ull rcp2(ull v) {
    float a, b; upk(v, a, b); return pk(frcp(a), frcp(b));
}

// ---------------- device globals (scratch; zeroed each launch by hx_init) ---
#define VSTRIDE 16                   // 64B per value -> spread across LTS slices
__device__ unsigned g_bar;
__device__ unsigned g_h0[2048];
__device__ unsigned g_h1[2048];
__device__ unsigned g_h2[1024];
__device__ float    g_sum[3][22 * VSTRIDE];   // 3-deep rotating global accumulators

__global__ void hx_init() {
    int t = blockIdx.x * blockDim.x + threadIdx.x;
    int n = gridDim.x * blockDim.x;
    if (t == 0) g_bar = 0u;
    for (int i = t; i < 3 * 22 * VSTRIDE; i += n) ((float*)g_sum)[i] = 0.f;
    for (int i = t; i < 2048; i += n) { g_h0[i] = 0u; g_h1[i] = 0u; }
    for (int i = t; i < 1024; i += n) g_h2[i] = 0u;
}

// ---------------- software grid barrier (148 co-resident CTAs) ---------------
// Single-counter atomic+spin: measured fastest across 5 barrier designs.
__device__ __forceinline__ void gsync(unsigned target) {
    __syncthreads();
    if (threadIdx.x == 0) {
        __threadfence();
        atomicAdd(&g_bar, 1u);
        while (*(volatile unsigned*)&g_bar < target) { }
        __threadfence();
    }
    __syncthreads();
}

// ---------------- warp-0 bin search for radix select -------------------------
__device__ __forceinline__ void find_bin(const unsigned* hist, int nb, unsigned r,
                                         unsigned* sel_out) {
    int lane = threadIdx.x & 31;
    int ch = nb >> 5;
    unsigned csum = 0;
    for (int i = 0; i < ch; ++i) csum += __ldcg(&hist[lane * ch + i]);
    unsigned inc = csum;
#pragma unroll
    for (int off = 1; off < 32; off <<= 1) {
        unsigned t = __shfl_up_sync(0xffffffffu, inc, off);
        if (lane >= off) inc += t;
    }
    unsigned excl = inc - csum;
    bool has = (r >= excl) && (r < inc);
    unsigned m = __ballot_sync(0xffffffffu, has);
    int sel = __ffs(m) - 1;
    unsigned bin = 0, before = 0;
    if (lane == sel) {
        unsigned c = excl;
        for (int i = 0; i < ch; ++i) {
            unsigned h = __ldcg(&hist[sel * ch + i]);
            if (r < c + h) { bin = (unsigned)(sel * ch + i); before = c; break; }
            c += h;
        }
    }
    bin    = __shfl_sync(0xffffffffu, bin, sel);
    before = __shfl_sync(0xffffffffu, before, sel);
    if (lane == 0) { sel_out[0] = bin; sel_out[1] = before; }
}

// warp-aggregated histogram add (all 32 lanes participate)
__device__ __forceinline__ void hist_add(unsigned* sHist, unsigned bin, bool active) {
    unsigned key = active ? bin : 0xffffffffu;
    unsigned mask = __match_any_sync(0xffffffffu, key);
    int leader = __ffs(mask) - 1;
    if (active && (int)(threadIdx.x & 31) == leader)
        atomicAdd(&sHist[bin], (unsigned)__popc(mask));
}

// ---------------- the persistent kernel --------------------------------------
__global__ void __launch_bounds__(TPB, 1)
he_norm_kernel(const float* __restrict__ pic, const float* __restrict__ Wt,
               const float* __restrict__ HtRM, const float* __restrict__ W0,
               const float* __restrict__ H0, float* __restrict__ out) {
    extern __shared__ float smem[];
    // 7 SoA planes of PIXPAD floats: Wx Wy Wz Ww V0 V1 V2 (contiguous)
    float*    sP    = smem;
    float*    sWx   = sP + 0 * PIXPAD;
    float*    sWy   = sP + 1 * PIXPAD;
    float*    sWz   = sP + 2 * PIXPAD;
    float*    sWw   = sP + 3 * PIXPAD;
    float*    sV0   = sP + 4 * PIXPAD;
    float*    sV1   = sP + 5 * PIXPAD;
    float*    sV2   = sP + 6 * PIXPAD;
    unsigned* sHist = (unsigned*)(sP + 7 * PIXPAD);      // 2048 u32
    float*    sRed  = (float*)(sHist + 2048);            // NWARP*22
    float*    sB    = sRed + NWARP * 22;                 // 24
    unsigned* sSel  = (unsigned*)(sB + 24);              // 2

    const int tid  = threadIdx.x;
    const int cta  = blockIdx.x;
    const int base = cta * PIXPAD;
    const int cnt  = max(0, min(PIXPAD, NPIX - base));   // valid pixels (even)

    // ---- prologue: W0 slice + V = -log(clip(pic)); zero pads -----------------
    const float4* W0v = (const float4*)W0;
    for (int p = tid; p < PIXPAD; p += TPB) {
        float4 w = (p < cnt) ? W0v[base + p] : make_float4(0.f, 0.f, 0.f, 0.f);
        sWx[p] = w.x; sWy[p] = w.y; sWz[p] = w.z; sWw[p] = w.w;
        float v0 = 0.f, v1 = 0.f, v2 = 0.f;
        if (p < cnt) {
            float x0 = pic[0 * NPIX + base + p];
            float x1 = pic[1 * NPIX + base + p];
            float x2 = pic[2 * NPIX + base + p];
            v0 = -__logf(fminf(fmaxf(x0, 0.01f), 0.99f));
            v1 = -__logf(fminf(fmaxf(x1, 0.01f), 0.99f));
            v2 = -__logf(fminf(fmaxf(x2, 0.01f), 0.99f));
        }
        sV0[p] = v0; sV1[p] = v1; sV2[p] = v2;
    }
    ull Hdp[12];
#pragma unroll
    for (int i = 0; i < 12; ++i) { float h = H0[i]; Hdp[i] = pk(h, h); }
    __syncthreads();

    const ull* pWx = (const ull*)sWx; const ull* pWy = (const ull*)sWy;
    const ull* pWz = (const ull*)sWz; const ull* pWw = (const ull*)sWw;
    const ull* pV0 = (const ull*)sV0; const ull* pV1 = (const ull*)sV1;
    const ull* pV2 = (const ull*)sV2;
    ull* qWx = (ull*)sWx; ull* qWy = (ull*)sWy; ull* qWz = (ull*)sWz; ull* qWw = (ull*)sWw;

    unsigned nsync = 0;
    const ull epsp = pk(EPSF, EPSF);
    const int lane = tid & 31, warp = tid >> 5;

    // ---- NMF multiplicative updates: 99 full iterations -----------------------
    for (int it = 0; it < NITER - 1; ++it) {
        ull acc[22];
#pragma unroll
        for (int i = 0; i < 22; ++i) acc[i] = 0ull;

#pragma unroll
        for (int k = 0; k < KTRIPS; ++k) {
            const int i = tid + k * TPB;                 // pair index, no bounds
            ull wx = pWx[i], wy = pWy[i], wz = pWz[i], ww = pWw[i];
            ull v0 = pV0[i], v1 = pV1[i], v2 = pV2[i];

            // t_j = sum_c v_c * Hd[c,j]
            ull t0, t1, t2, t3;
            MUL2(t0, v0, Hdp[0]);  FMA2(t0, v1, Hdp[4],  t0); FMA2(t0, v2, Hdp[8],  t0);
            MUL2(t1, v0, Hdp[1]);  FMA2(t1, v1, Hdp[5],  t1); FMA2(t1, v2, Hdp[9],  t1);
            MUL2(t2, v0, Hdp[2]);  FMA2(t2, v1, Hdp[6],  t2); FMA2(t2, v2, Hdp[10], t2);
            MUL2(t3, v0, Hdp[3]);  FMA2(t3, v1, Hdp[7],  t3); FMA2(t3, v2, Hdp[11], t3);

            // u_c = Hd[c,:] . w ;  d_j = eps + sum_c Hd[c,j]*u_c  (== (w @ G)_j + eps)
            ull u0, u1, u2;
            MUL2(u0, wx, Hdp[0]); FMA2(u0, wy, Hdp[1], u0); FMA2(u0, wz, Hdp[2],  u0); FMA2(u0, ww, Hdp[3],  u0);
            MUL2(u1, wx, Hdp[4]); FMA2(u1, wy, Hdp[5], u1); FMA2(u1, wz, Hdp[6],  u1); FMA2(u1, ww, Hdp[7],  u1);
            MUL2(u2, wx, Hdp[8]); FMA2(u2, wy, Hdp[9], u2); FMA2(u2, wz, Hdp[10], u2); FMA2(u2, ww, Hdp[11], u2);
            ull d0 = epsp, d1 = epsp, d2 = epsp, d3 = epsp;
            FMA2(d0, u0, Hdp[0], d0); FMA2(d0, u1, Hdp[4], d0); FMA2(d0, u2, Hdp[8],  d0);
            FMA2(d1, u0, Hdp[1], d1); FMA2(d1, u1, Hdp[5], d1); FMA2(d1, u2, Hdp[9],  d1);
            FMA2(d2, u0, Hdp[2], d2); FMA2(d2, u1, Hdp[6], d2); FMA2(d2, u2, Hdp[10], d2);
            FMA2(d3, u0, Hdp[3], d3); FMA2(d3, u1, Hdp[7], d3); FMA2(d3, u2, Hdp[11], d3);

            // quad-paired reciprocal: one rcp2 serves all four denominators
            ull p01, p23, pq, r, q01, q23, i0, i1, i2, i3;
            MUL2(p01, d0, d1); MUL2(p23, d2, d3);
            MUL2(pq, p01, p23);
            r = rcp2(pq);                 // 2 MUFU total (vs 8)
            MUL2(q01, p23, r);            // 1/(d0*d1)
            MUL2(q23, p01, r);            // 1/(d2*d3)
            MUL2(i0, d1, q01); MUL2(i1, d0, q01);
            MUL2(i2, d3, q23); MUL2(i3, d2, q23);

            // n_j = (w_j * t_j) * inv_j
            ull n0, n1, n2, n3;
            MUL2(n0, wx, t0); MUL2(n1, wy, t1); MUL2(n2, wz, t2); MUL2(n3, ww, t3);
            MUL2(n0, n0, i0); MUL2(n1, n1, i1); MUL2(n2, n2, i2); MUL2(n3, n3, i3);
            qWx[i] = n0; qWy[i] = n1; qWz[i] = n2; qWw[i] = n3;

            // S1 = V @ Wc_new (3x4)
            FMA2(acc[0],  v0, n0, acc[0]);  FMA2(acc[1],  v0, n1, acc[1]);
            FMA2(acc[2],  v0, n2, acc[2]);  FMA2(acc[3],  v0, n3, acc[3]);
            FMA2(acc[4],  v1, n0, acc[4]);  FMA2(acc[5],  v1, n1, acc[5]);
            FMA2(acc[6],  v1, n2, acc[6]);  FMA2(acc[7],  v1, n3, acc[7]);
            FMA2(acc[8],  v2, n0, acc[8]);  FMA2(acc[9],  v2, n1, acc[9]);
            FMA2(acc[10], v2, n2, acc[10]); FMA2(acc[11], v2, n3, acc[11]);
            // S2 = Wc_new^T Wc_new (10 uniques)
            FMA2(acc[12], n0, n0, acc[12]); FMA2(acc[13], n0, n1, acc[13]);
            FMA2(acc[14], n0, n2, acc[14]); FMA2(acc[15], n0, n3, acc[15]);
            FMA2(acc[16], n1, n1, acc[16]); FMA2(acc[17], n1, n2, acc[17]);
            FMA2(acc[18], n1, n3, acc[18]); FMA2(acc[19], n2, n2, acc[19]);
            FMA2(acc[20], n2, n3, acc[20]); FMA2(acc[21], n3, n3, acc[21]);
        }

        // fold packed halves; block reduce 22 accumulators
        float accs[22];
#pragma unroll
        for (int i = 0; i < 22; ++i) { float a, b; upk(acc[i], a, b); accs[i] = a + b; }
#pragma unroll
        for (int i = 0; i < 22; ++i) {
            float v = accs[i];
#pragma unroll
            for (int off = 16; off > 0; off >>= 1) v += __shfl_down_sync(0xffffffffu, v, off);
            accs[i] = v;
        }
        if (lane == 0) {
#pragma unroll
            for (int i = 0; i < 22; ++i) sRed[warp * 22 + i] = accs[i];
        }
        __syncthreads();
        const int buf = it % 3;
        if (tid < 22) {
            float s = 0.f;
#pragma unroll
            for (int w = 0; w < NWARP; ++w) s += sRed[w * 22 + tid];
            atomicAdd(&g_sum[buf][tid * VSTRIDE], s);    // pre-barrier global accumulate
        }
        gsync(++nsync * NCTA);

        // post-barrier: one broadcast load per value (no 148-element scan)
        if (tid < 22) sB[tid] = __ldcg(&g_sum[buf][tid * VSTRIDE]);
        // zero the buffer that iteration it+2 will reuse (its readers finished
        // before this barrier; its writers start only after the next barrier,
        // whose arrival fence publishes this store)
        if (cta < 22 && tid == 0) g_sum[(it + 2) % 3][cta * VSTRIDE] = 0.f;
        __syncthreads();

        // Hd update (redundant, deterministic in every thread)
        float hd[12];
#pragma unroll
        for (int i = 0; i < 12; ++i) { float a, b; upk(Hdp[i], a, b); hd[i] = a; }
        float S2[16];
        {
            float p00 = sB[12], p01 = sB[13], p02 = sB[14], p03 = sB[15];
            float p11 = sB[16], p12 = sB[17], p13 = sB[18];
            float p22 = sB[19], p23 = sB[20], p33 = sB[21];
            S2[0]=p00; S2[1]=p01; S2[2]=p02; S2[3]=p03;
            S2[4]=p01; S2[5]=p11; S2[6]=p12; S2[7]=p13;
            S2[8]=p02; S2[9]=p12; S2[10]=p22; S2[11]=p23;
            S2[12]=p03; S2[13]=p13; S2[14]=p23; S2[15]=p33;
        }
#pragma unroll
        for (int c = 0; c < 3; ++c)
#pragma unroll
            for (int j = 0; j < 4; ++j) {
                float den = hd[c*4+0]*S2[0*4+j] + hd[c*4+1]*S2[1*4+j]
                          + hd[c*4+2]*S2[2*4+j] + hd[c*4+3]*S2[3*4+j] + EPSF;
                float hn = hd[c*4+j] * sB[c*4+j] * frcp(den);
                Hdp[c*4+j] = pk(hn, hn);
            }
    }

    // ---- final iteration: Wc update only (sums + Hd update are dead work) -----
#pragma unroll
    for (int k = 0; k < KTRIPS; ++k) {
        const int i = tid + k * TPB;
        ull wx = pWx[i], wy = pWy[i], wz = pWz[i], ww = pWw[i];
        ull v0 = pV0[i], v1 = pV1[i], v2 = pV2[i];
        ull t0, t1, t2, t3;
        MUL2(t0, v0, Hdp[0]);  FMA2(t0, v1, Hdp[4],  t0); FMA2(t0, v2, Hdp[8],  t0);
        MUL2(t1, v0, Hdp[1]);  FMA2(t1, v1, Hdp[5],  t1); FMA2(t1, v2, Hdp[9],  t1);
        MUL2(t2, v0, Hdp[2]);  FMA2(t2, v1, Hdp[6],  t2); FMA2(t2, v2, Hdp[10], t2);
        MUL2(t3, v0, Hdp[3]);  FMA2(t3, v1, Hdp[7],  t3); FMA2(t3, v2, Hdp[11], t3);
        ull u0, u1, u2;
        MUL2(u0, wx, Hdp[0]); FMA2(u0, wy, Hdp[1], u0); FMA2(u0, wz, Hdp[2],  u0); FMA2(u0, ww, Hdp[3],  u0);
        MUL2(u1, wx, Hdp[4]); FMA2(u1, wy, Hdp[5], u1); FMA2(u1, wz, Hdp[6],  u1); FMA2(u1, ww, Hdp[7],  u1);
        MUL2(u2, wx, Hdp[8]); FMA2(u2, wy, Hdp[9], u2); FMA2(u2, wz, Hdp[10], u2); FMA2(u2, ww, Hdp[11], u2);
        ull d0 = epsp, d1 = epsp, d2 = epsp, d3 = epsp;
        FMA2(d0, u0, Hdp[0], d0); FMA2(d0, u1, Hdp[4], d0); FMA2(d0, u2, Hdp[8],  d0);
        FMA2(d1, u0, Hdp[1], d1); FMA2(d1, u1, Hdp[5], d1); FMA2(d1, u2, Hdp[9],  d1);
        FMA2(d2, u0, Hdp[2], d2); FMA2(d2, u1, Hdp[6], d2); FMA2(d2, u2, Hdp[10], d2);
        FMA2(d3, u0, Hdp[3], d3); FMA2(d3, u1, Hdp[7], d3); FMA2(d3, u2, Hdp[11], d3);
        ull p01, p23, pq, r, q01, q23, i0, i1, i2, i3;
        MUL2(p01, d0, d1); MUL2(p23, d2, d3);
        MUL2(pq, p01, p23);
        r = rcp2(pq);
        MUL2(q01, p23, r); MUL2(q23, p01, r);
        MUL2(i0, d1, q01); MUL2(i1, d0, q01);
        MUL2(i2, d3, q23); MUL2(i3, d2, q23);
        ull n0, n1, n2, n3;
        MUL2(n0, wx, t0); MUL2(n1, wy, t1); MUL2(n2, wz, t2); MUL2(n3, ww, t3);
        MUL2(n0, n0, i0); MUL2(n1, n1, i1); MUL2(n2, n2, i2); MUL2(n3, n3, i3);
        qWx[i] = n0; qWy[i] = n1; qWz[i] = n2; qWw[i] = n3;
    }
    __syncthreads();

    // ---- global 0.99-quantile: 3-round radix select ---------------------------
    float pos = 0.99f * (float)(4 * NPIX - 1);
    unsigned lo = (unsigned)pos;
    float fr = pos - (float)lo;
    unsigned rank = lo + (fr > 0.5f ? 1u : 0u);
    rank += (unsigned)(4 * (NCTA * PIXPAD - NPIX));      // pad zeros sit below quantile

    const int tot = 4 * PIXPAD;                          // the 4 W planes, no bounds
    unsigned b0, b1, b2;

    // round 0: bits [31:21]
    for (int i = tid; i < 2048; i += TPB) sHist[i] = 0u;
    __syncthreads();
    for (int i = tid; i < tot; i += TPB) {
        unsigned k = __float_as_uint(sP[i]);
        hist_add(sHist, k >> 21, true);
    }
    __syncthreads();
    for (int i = tid; i < 2048; i += TPB) { unsigned h = sHist[i]; if (h) atomicAdd(&g_h0[i], h); }
    gsync(++nsync * NCTA);
    if (tid < 32) find_bin(g_h0, 2048, rank, sSel);
    __syncthreads();
    b0 = sSel[0]; rank -= sSel[1];

    // round 1: bits [20:10]
    for (int i = tid; i < 2048; i += TPB) sHist[i] = 0u;
    __syncthreads();
    for (int i = tid; i < tot; i += TPB) {
        unsigned k = __float_as_uint(sP[i]);
        hist_add(sHist, (k >> 10) & 2047u, (k >> 21) == b0);
    }
    __syncthreads();
    for (int i = tid; i < 2048; i += TPB) { unsigned h = sHist[i]; if (h) atomicAdd(&g_h1[i], h); }
    gsync(++nsync * NCTA);
    if (tid < 32) find_bin(g_h1, 2048, rank, sSel);
    __syncthreads();
    b1 = sSel[0]; rank -= sSel[1];

    // round 2: bits [9:0]
    for (int i = tid; i < 1024; i += TPB) sHist[i] = 0u;
    __syncthreads();
    unsigned pref = (b0 << 11) | b1;
    for (int i = tid; i < tot; i += TPB) {
        unsigned k = __float_as_uint(sP[i]);
        hist_add(sHist, k & 1023u, (k >> 10) == pref);
    }
    __syncthreads();
    for (int i = tid; i < 1024; i += TPB) { unsigned h = sHist[i]; if (h) atomicAdd(&g_h2[i], h); }
    gsync(++nsync * NCTA);
    if (tid < 32) find_bin(g_h2, 1024, rank, sSel);
    __syncthreads();
    b2 = sSel[0];

    float qv = __uint_as_float((b0 << 21) | (b1 << 10) | b2);

    // ---- epilogue: out = clip(exp(-(W_target @ (Wc^T * Ht/q))), 0, 1) ---------
    float s = HtRM[0] * frcp(qv);
    float w0 = Wt[0]*s,  w1 = Wt[1]*s,  w2 = Wt[2]*s,  w3 = Wt[3]*s;
    float w4 = Wt[4]*s,  w5 = Wt[5]*s,  w6 = Wt[6]*s,  w7 = Wt[7]*s;
    float w8 = Wt[8]*s,  w9 = Wt[9]*s,  wA = Wt[10]*s, wB = Wt[11]*s;
    for (int p = tid; p < cnt; p += TPB) {
        float x = sWx[p], y = sWy[p], z = sWz[p], w = sWw[p];
        float a0 = w0*x + w1*y + w2*z + w3*w;
        float a1 = w4*x + w5*y + w6*z + w7*w;
        float a2 = w8*x + w9*y + wA*z + wB*w;
        out[0*NPIX + base + p] = __saturatef(__expf(-a0));
        out[1*NPIX + base + p] = __saturatef(__expf(-a1));
        out[2*NPIX + base + p] = __saturatef(__expf(-a2));
    }
}

// ---------------- launch -------------------------------------------------------
extern "C" void kernel_launch(void* const* d_in, const int* in_sizes, int n_in,
                              void* d_out, int out_size) {
    const float *pic = nullptr, *Wt = nullptr, *Htq = nullptr, *W0 = nullptr, *H0 = nullptr;
    for (int i = 0; i < n_in; ++i) {
        int sz = in_sizes[i];
        if      (sz == 3 * NPIX) pic = (const float*)d_in[i];
        else if (sz == 4 * NPIX) W0  = (const float*)d_in[i];
        else if (sz == 1)        Htq = (const float*)d_in[i];
        else if (sz == 12) { if (!Wt) Wt = (const float*)d_in[i]; else H0 = (const float*)d_in[i]; }
    }
    float* out = (float*)d_out;

    const size_t smem_bytes =
        (size_t)7 * PIXPAD * 4 +      // 7 SoA planes (200704)
        2048 * 4 +                    // sHist
        NWARP * 22 * 4 +              // sRed
        24 * 4 + 2 * 4 + 64;          // sB + sSel + pad

    cudaFuncSetAttribute(he_norm_kernel, cudaFuncAttributeMaxDynamicSharedMemorySize,
                         (int)smem_bytes);

    hx_init<<<4, 512>>>();
    he_norm_kernel<<<NCTA, TPB, smem_bytes>>>(pic, Wt, Htq, W0, H0, out);
}